// round 16
// baseline (speedup 1.0000x reference)
#include <cuda_runtime.h>
#include <cuda_bf16.h>
#include <cstdint>

#define ALPHA 0.01f

// ---------------------------------------------------------------------------
// Scratch (static device globals — allocation-free per harness rules)
// ---------------------------------------------------------------------------
__device__ float g_h1[32u*64u*112u*112u];        // 102.8 MB conv1 pooled out (fp32)
__device__ float g_h2[32u*64u*56u*56u];          //  25.7 MB conv2 pooled out
__device__ float g_fcp[196*32*10];               // FC split-K partials
__device__ unsigned long long g_w2t_hi[9*1024];  // w2 [tap][oc][ic] bf16 hi (16 ULL/oc)
__device__ unsigned long long g_w2t_lo[9*1024];  // ... bf16 lo
__device__ unsigned long long g_w1t_hi[640];     // w1 [oc][k0..39] bf16 hi
__device__ unsigned long long g_w1t_lo[640];     // ... bf16 lo

__device__ __forceinline__ uint32_t smem_to_u32(const void* p) {
    uint32_t a;
    asm("{ .reg .u64 t; cvta.to.shared.u64 t, %1; cvt.u32.u64 %0, t; }" : "=r"(a) : "l"(p));
    return a;
}
__device__ __forceinline__ void ldsm_x4(uint32_t* r, uint32_t addr) {
    asm volatile("ldmatrix.sync.aligned.m8n8.x4.shared.b16 {%0,%1,%2,%3}, [%4];"
                 : "=r"(r[0]), "=r"(r[1]), "=r"(r[2]), "=r"(r[3]) : "r"(addr));
}
__device__ __forceinline__ void mma_bf16(float* d, const uint32_t* a,
                                         uint32_t b0, uint32_t b1) {
    asm volatile("mma.sync.aligned.m16n8k16.row.col.f32.bf16.bf16.f32 "
                 "{%0,%1,%2,%3}, {%4,%5,%6,%7}, {%8,%9}, {%0,%1,%2,%3};"
                 : "+f"(d[0]), "+f"(d[1]), "+f"(d[2]), "+f"(d[3])
                 : "r"(a[0]), "r"(a[1]), "r"(a[2]), "r"(a[3]), "r"(b0), "r"(b1));
}
__device__ __forceinline__ void cp_async16(uint32_t dst, const void* src) {
    asm volatile("cp.async.cg.shared.global [%0], [%1], 16;" :: "r"(dst), "l"(src));
}
#define CP_COMMIT() asm volatile("cp.async.commit_group;" ::: "memory")
#define CP_WAIT0()  asm volatile("cp.async.wait_group 0;" ::: "memory")

__device__ __forceinline__ float leaky(float v) { return v > 0.f ? v : ALPHA * v; }

// ---------------------------------------------------------------------------
// Kernel 0a: w2 -> g_w2t_{hi,lo}[tap][oc][ic] bf16 (proven)
// ---------------------------------------------------------------------------
__global__ void prep_w2_kernel(const float* __restrict__ w2)
{
    int i = blockIdx.x * blockDim.x + threadIdx.x;
    if (i >= 9*64*64) return;
    int tap = i / 4096, r = i % 4096;
    int oc = r / 64, ic = r % 64;
    float v = w2[(oc*64 + ic)*9 + tap];
    __nv_bfloat16 hi = __float2bfloat16(v);
    __nv_bfloat16 lo = __float2bfloat16(v - __bfloat162float(hi));
    ((__nv_bfloat16*)g_w2t_hi)[i] = hi;
    ((__nv_bfloat16*)g_w2t_lo)[i] = lo;
}

// ---------------------------------------------------------------------------
// Kernel 0b: w1 -> g_w1t_{hi,lo}[oc][k] bf16, k = c*9+ky*3+kx (27 real, pad 40)
// ---------------------------------------------------------------------------
__global__ void prep_w1_kernel(const float* __restrict__ w1)
{
    int i = blockIdx.x * blockDim.x + threadIdx.x;
    if (i >= 64*40) return;
    int oc = i / 40, k = i % 40;
    float v = (k < 27) ? w1[oc*27 + k] : 0.f;
    __nv_bfloat16 hi = __float2bfloat16(v);
    __nv_bfloat16 lo = __float2bfloat16(v - __bfloat162float(hi));
    ((__nv_bfloat16*)g_w1t_hi)[i] = hi;
    ((__nv_bfloat16*)g_w1t_lo)[i] = lo;
}

// ---------------------------------------------------------------------------
// Kernel 1: conv1(3->64) + leaky + maxpool2 via mma.sync (im2col K=27->32).
// R16: 256-px tiles (16x16 conv), grid (196,32); weights via cp.async
// (hidden behind x-staging + im2col); 96 mma/warp; ~70KB smem -> 2 CTA/SM.
// A/B rows 80B (bank-walk conflict-free, verified in R12).
// ---------------------------------------------------------------------------
#define C1_X     256                        // 972 floats -> ends 4144
#define C1_AHI   4160                       // 256*80 = 20480
#define C1_ALO   24640
#define C1_BHI   45120                      // 64*80 = 5120
#define C1_BLO   50240
#define C1_TOTAL 69696                      // D overlay 256*64*4 from C1_AHI

__global__ __launch_bounds__(256) void conv1_kernel(const float* __restrict__ x,
                                                    const float* __restrict__ b1)
{
    extern __shared__ __align__(16) char smem[];
    const uint32_t sb = smem_to_u32(smem);
    const int tid  = threadIdx.x;
    const int lane = tid & 31;
    const int wid  = tid >> 5;

    const int t = blockIdx.x;               // 0..195 = 14 (y) x 14 (x)
    const int b = blockIdx.y;
    const int cy0 = (t / 14) * 16;          // conv-space origin
    const int cx0 = (t % 14) * 16;

    float* s_bias = (float*)smem;
    float* s_x    = (float*)(smem + C1_X);  // [3][18][18]
    if (tid < 64) s_bias[tid] = b1[tid];

    // B via cp.async (overlaps x staging + im2col below)
    for (int i = tid; i < 320; i += 256) {
        cp_async16(sb + C1_BHI + i*16, (const char*)g_w1t_hi + i*16);
        cp_async16(sb + C1_BLO + i*16, (const char*)g_w1t_lo + i*16);
    }
    CP_COMMIT();

    // raw x halo 18x18x3
    for (int i = tid; i < 972; i += 256) {
        int c = i / 324, pos = i % 324;
        int r = pos / 18, col = pos % 18;
        int gy = cy0 - 1 + r, gx = cx0 - 1 + col;
        float v = 0.f;
        if (gy >= 0 && gy < 224 && gx >= 0 && gx < 224)
            v = x[((b*3 + c)*224 + gy)*224 + gx];
        s_x[i] = v;
    }
    __syncthreads();

    // im2col A[p][k] hi/lo (rows 80B; k 0..31, 27 real)
    {
        __nv_bfloat16* a_hi = (__nv_bfloat16*)(smem + C1_AHI);
        __nv_bfloat16* a_lo = (__nv_bfloat16*)(smem + C1_ALO);
        for (int i = tid; i < 256*32; i += 256) {
            int p = i >> 5, k = i & 31;
            float v = 0.f;
            if (k < 27) {
                int c = k / 9, rem = k % 9;
                int ky = rem / 3, kx = rem % 3;
                int py = p >> 4, px = p & 15;
                v = s_x[c*324 + (py + ky)*18 + (px + kx)];
            }
            __nv_bfloat16 hi = __float2bfloat16(v);
            __nv_bfloat16 lo = __float2bfloat16(v - __bfloat162float(hi));
            a_hi[p*40 + k] = hi;
            a_lo[p*40 + k] = lo;
        }
    }
    CP_WAIT0();
    __syncthreads();

    // mainloop: warp w -> pixels [32w, 32w+32), all 64 oc
    uint32_t aBase[2];
    #pragma unroll
    for (int f = 0; f < 2; f++) {
        int p = wid*32 + f*16 + (lane & 15);
        aBase[f] = sb + C1_AHI + (uint32_t)p*80u + (uint32_t)(lane >> 4)*16u;
    }
    uint32_t bBase[4];
    #pragma unroll
    for (int nb = 0; nb < 4; nb++) {
        int ocrow = nb*16 + (lane & 7) + ((lane >> 4) & 1)*8;
        bBase[nb] = sb + C1_BHI + (uint32_t)ocrow*80u + (uint32_t)((lane >> 3) & 1)*16u;
    }

    float acc[2][8][4];
    #pragma unroll
    for (int f = 0; f < 2; f++)
        #pragma unroll
        for (int nf = 0; nf < 8; nf++)
            #pragma unroll
            for (int c = 0; c < 4; c++) acc[f][nf][c] = 0.f;

    #pragma unroll
    for (int k = 0; k < 2; k++) {
        const uint32_t ko = (uint32_t)k * 32u;
        uint32_t ah[2][4], al[2][4];
        ldsm_x4(ah[0], aBase[0] + ko);
        ldsm_x4(ah[1], aBase[1] + ko);
        ldsm_x4(al[0], aBase[0] + (C1_ALO - C1_AHI) + ko);
        ldsm_x4(al[1], aBase[1] + (C1_ALO - C1_AHI) + ko);
        #pragma unroll
        for (int nb = 0; nb < 4; nb++) {
            uint32_t bh[4], bl[4];
            ldsm_x4(bh, bBase[nb] + ko);
            ldsm_x4(bl, bBase[nb] + (C1_BLO - C1_BHI) + ko);
            #pragma unroll
            for (int f = 0; f < 2; f++) {
                mma_bf16(acc[f][2*nb],   ah[f], bh[0], bh[1]);   // hi*hi
                mma_bf16(acc[f][2*nb+1], ah[f], bh[2], bh[3]);
                mma_bf16(acc[f][2*nb],   ah[f], bl[0], bl[1]);   // hi*lo
                mma_bf16(acc[f][2*nb+1], ah[f], bl[2], bl[3]);
                mma_bf16(acc[f][2*nb],   al[f], bh[0], bh[1]);   // lo*hi
                mma_bf16(acc[f][2*nb+1], al[f], bh[2], bh[3]);
            }
        }
    }
    __syncthreads();   // A reads done before D overlay

    // D stage [p][oc] (proven m16n8 layout), overlays A
    float* s_d = (float*)(smem + C1_AHI);
    #pragma unroll
    for (int f = 0; f < 2; f++)
        #pragma unroll
        for (int nf = 0; nf < 8; nf++) {
            int oc = nf*8 + 2*(lane & 3);
            int p0 = wid*32 + f*16 + (lane >> 2);
            s_d[p0*64 + oc]         = acc[f][nf][0];
            s_d[p0*64 + oc + 1]     = acc[f][nf][1];
            s_d[(p0+8)*64 + oc]     = acc[f][nf][2];
            s_d[(p0+8)*64 + oc + 1] = acc[f][nf][3];
        }
    __syncthreads();

    // pooled 8x8 x 64 oc: thread -> q = tid/4, 16 oc
    {
        int q   = tid >> 2;                 // 0..63
        int oc0 = (tid & 3) * 16;
        int qy = q >> 3, qx = q & 7;
        int p00 = (qy*2)*16 + qx*2;         // conv px (2qy, 2qx), row stride 16
        int oy = (cy0 >> 1) + qy, ox = (cx0 >> 1) + qx;
        #pragma unroll
        for (int j = 0; j < 16; j++) {
            int oc = oc0 + j;
            float m = fmaxf(fmaxf(s_d[p00*64 + oc],      s_d[(p00+1)*64 + oc]),
                            fmaxf(s_d[(p00+16)*64 + oc], s_d[(p00+17)*64 + oc]));
            g_h1[(((unsigned)(b*64 + oc))*112u + oy)*112u + ox] = leaky(m + s_bias[oc]);
        }
    }
}

// ---------------------------------------------------------------------------
// Kernel 2: conv2 via mma.sync + cp.async double-buffered weights (R15 proven)
// ---------------------------------------------------------------------------
#define C2_AHI     256
#define C2_ALO     26176
#define C2_W0      52096
#define C2_WSTRIDE 18432
#define C2_WLO_D   9216
#define C2_TOTAL   88960
#define C2_ALO_D   25920

__device__ __forceinline__ void c2_issue_w(uint32_t sb, int tap, int stage, int tid)
{
    const char* ghi = (const char*)g_w2t_hi + tap*8192;
    const char* glo = (const char*)g_w2t_lo + tap*8192;
    uint32_t whi = sb + C2_W0 + (uint32_t)stage*C2_WSTRIDE;
    for (int i = tid; i < 512; i += 256) {
        int oc = i >> 3, j = i & 7;
        uint32_t d = whi + (uint32_t)oc*144u + (uint32_t)j*16u;
        cp_async16(d,            ghi + i*16);
        cp_async16(d + C2_WLO_D, glo + i*16);
    }
}

__global__ __launch_bounds__(256, 2) void conv2_kernel(const float* __restrict__ b2)
{
    extern __shared__ __align__(16) char smem[];
    const uint32_t sb = smem_to_u32(smem);
    const int tid  = threadIdx.x;
    const int lane = tid & 31;
    const int wid  = tid >> 5;

    const int t = blockIdx.x;
    const int b = blockIdx.y;
    const int cy0 = (t / 14) * 16;
    const int cx0 = (t % 14) * 8;

    float* s_bias = (float*)smem;
    if (tid < 64) s_bias[tid] = b2[tid];

    c2_issue_w(sb, 0, 0, tid);
    CP_COMMIT();

    {
        __nv_bfloat16* s_ahi = (__nv_bfloat16*)(smem + C2_AHI);
        __nv_bfloat16* s_alo = (__nv_bfloat16*)(smem + C2_ALO);
        for (int i = tid; i < 64*180; i += 256) {
            int ic  = i / 180;
            int pos = i % 180;
            int r = pos / 10, c = pos % 10;
            int gy = cy0 - 1 + r, gx = cx0 - 1 + c;
            float v = 0.f;
            if (gy >= 0 && gy < 112 && gx >= 0 && gx < 112)
                v = g_h1[(((unsigned)(b*64 + ic))*112u + gy)*112u + gx];
            __nv_bfloat16 hi = __float2bfloat16(v);
            __nv_bfloat16 lo = __float2bfloat16(v - __bfloat162float(hi));
            s_ahi[pos*72 + ic] = hi;
            s_alo[pos*72 + ic] = lo;
        }
    }
    CP_WAIT0();
    __syncthreads();

    const int m_tile = wid & 3;
    const int n_tile = wid >> 2;

    uint32_t aBase[2];
    #pragma unroll
    for (int f = 0; f < 2; f++) {
        int p = m_tile*32 + f*16 + (lane & 15);
        int pos = (p >> 3)*10 + (p & 7);
        aBase[f] = sb + C2_AHI + (uint32_t)pos*144u + (uint32_t)(lane >> 4)*16u;
    }
    uint32_t bOff[2];
    #pragma unroll
    for (int nb = 0; nb < 2; nb++) {
        int ocrow = n_tile*32 + nb*16 + (lane & 7) + ((lane >> 4) & 1)*8;
        bOff[nb] = (uint32_t)ocrow*144u + (uint32_t)((lane >> 3) & 1)*16u;
    }

    float acc[2][4][4];
    #pragma unroll
    for (int f = 0; f < 2; f++)
        #pragma unroll
        for (int nf = 0; nf < 4; nf++)
            #pragma unroll
            for (int c = 0; c < 4; c++) acc[f][nf][c] = 0.f;

    for (int tap = 0; tap < 9; tap++) {
        const int stage = tap & 1;
        if (tap < 8) { c2_issue_w(sb, tap+1, stage ^ 1, tid); CP_COMMIT(); }

        const uint32_t wbase = sb + C2_W0 + (uint32_t)stage*C2_WSTRIDE;
        const uint32_t aS = (uint32_t)((tap/3)*10 + (tap%3)) * 144u;
        #pragma unroll
        for (int k = 0; k < 4; k++) {
            const uint32_t ko = (uint32_t)k * 32u;
            uint32_t ah[2][4], al[2][4];
            ldsm_x4(ah[0], aBase[0] + aS + ko);
            ldsm_x4(ah[1], aBase[1] + aS + ko);
            ldsm_x4(al[0], aBase[0] + C2_ALO_D + aS + ko);
            ldsm_x4(al[1], aBase[1] + C2_ALO_D + aS + ko);
            #pragma unroll
            for (int nb = 0; nb < 2; nb++) {
                uint32_t bh[4], bl[4];
                const uint32_t bbadr = wbase + bOff[nb] + ko;
                ldsm_x4(bh, bbadr);
                ldsm_x4(bl, bbadr + C2_WLO_D);
                #pragma unroll
                for (int f = 0; f < 2; f++) {
                    mma_bf16(acc[f][2*nb],   ah[f], bh[0], bh[1]);
                    mma_bf16(acc[f][2*nb+1], ah[f], bh[2], bh[3]);
                    mma_bf16(acc[f][2*nb],   ah[f], bl[0], bl[1]);
                    mma_bf16(acc[f][2*nb+1], ah[f], bl[2], bl[3]);
                    mma_bf16(acc[f][2*nb],   al[f], bh[0], bh[1]);
                    mma_bf16(acc[f][2*nb+1], al[f], bh[2], bh[3]);
                }
            }
        }
        if (tap < 8) CP_WAIT0();
        __syncthreads();
    }

    float* s_d = (float*)(smem + C2_AHI);
    #pragma unroll
    for (int f = 0; f < 2; f++)
        #pragma unroll
        for (int nf = 0; nf < 4; nf++) {
            int oc = n_tile*32 + nf*8 + 2*(lane & 3);
            int p0 = m_tile*32 + f*16 + (lane >> 2);
            s_d[p0*64 + oc]         = acc[f][nf][0];
            s_d[p0*64 + oc + 1]     = acc[f][nf][1];
            s_d[(p0+8)*64 + oc]     = acc[f][nf][2];
            s_d[(p0+8)*64 + oc + 1] = acc[f][nf][3];
        }
    __syncthreads();

    {
        int q   = tid >> 3;
        int oc0 = (tid & 7) * 8;
        int qy = q >> 2, qx = q & 3;
        int p00 = (qy*2)*8 + qx*2;
        int oy = (cy0 >> 1) + qy, ox = (cx0 >> 1) + qx;
        #pragma unroll
        for (int j = 0; j < 8; j++) {
            int oc = oc0 + j;
            float m = fmaxf(fmaxf(s_d[p00*64 + oc],     s_d[(p00+1)*64 + oc]),
                            fmaxf(s_d[(p00+8)*64 + oc], s_d[(p00+9)*64 + oc]));
            g_h2[(((unsigned)(b*64 + oc))*56u + oy)*56u + ox] = leaky(m + s_bias[oc]);
        }
    }
}

// ---------------------------------------------------------------------------
// Kernel 3: FC split-K partials, grid (196,4), warp = batch, 8-deep prefetch
// ---------------------------------------------------------------------------
__global__ __launch_bounds__(256) void fc_partial_kernel(const float* __restrict__ wfc)
{
    __shared__ __align__(16) float s_wt[10][1024];
    const int tid = threadIdx.x;
    const int k0  = blockIdx.x * 1024;

    for (int i = tid; i < 10240; i += 256) {
        int k = i / 10, c = i % 10;
        s_wt[c][k] = wfc[k0*10 + i];
    }
    __syncthreads();

    const int warp = tid >> 5, lane = tid & 31;
    const int b = blockIdx.y * 8 + warp;

    const float4* hb = (const float4*)&g_h2[b*200704 + k0];
    float4 hv[8];
    #pragma unroll
    for (int j = 0; j < 8; j++) hv[j] = hb[lane + 32*j];

    float acc[10];
    #pragma unroll
    for (int c = 0; c < 10; c++) acc[c] = 0.f;

    #pragma unroll
    for (int j = 0; j < 8; j++) {
        int k4 = lane + 32*j;
        #pragma unroll
        for (int c = 0; c < 10; c++) {
            float4 wv = *(const float4*)&s_wt[c][k4*4];
            acc[c] += hv[j].x*wv.x + hv[j].y*wv.y + hv[j].z*wv.z + hv[j].w*wv.w;
        }
    }
    #pragma unroll
    for (int c = 0; c < 10; c++) {
        #pragma unroll
        for (int off = 16; off; off >>= 1)
            acc[c] += __shfl_xor_sync(0xffffffffu, acc[c], off);
    }
    if (lane == 0) {
        #pragma unroll
        for (int c = 0; c < 10; c++)
            g_fcp[(blockIdx.x*32 + b)*10 + c] = acc[c];
    }
}

// ---------------------------------------------------------------------------
// Kernel 4: final deterministic reduction (proven)
// ---------------------------------------------------------------------------
__global__ __launch_bounds__(224) void fc_reduce_kernel(const float* __restrict__ bfc,
                                                        float* __restrict__ out)
{
    __shared__ float s_part[7][10];
    const int tid = threadIdx.x;
    const int b   = blockIdx.x;
    const int warp = tid >> 5, lane = tid & 31;

    float a[10];
    #pragma unroll
    for (int c = 0; c < 10; c++) a[c] = 0.f;

    if (tid < 196) {
        const float2* p = (const float2*)&g_fcp[(tid*32 + b)*10];
        #pragma unroll
        for (int h = 0; h < 5; h++) {
            float2 v = p[h];
            a[2*h]   = v.x;
            a[2*h+1] = v.y;
        }
    }
    #pragma unroll
    for (int c = 0; c < 10; c++) {
        #pragma unroll
        for (int off = 16; off; off >>= 1)
            a[c] += __shfl_xor_sync(0xffffffffu, a[c], off);
    }
    if (lane == 0)
        #pragma unroll
        for (int c = 0; c < 10; c++) s_part[warp][c] = a[c];
    __syncthreads();

    if (tid < 10) {
        float s = bfc[tid];
        #pragma unroll
        for (int w = 0; w < 7; w++) s += s_part[w][tid];
        out[b*10 + tid] = s;
    }
}

// ---------------------------------------------------------------------------
extern "C" void kernel_launch(void* const* d_in, const int* in_sizes, int n_in,
                              void* d_out, int out_size)
{
    const float* x   = (const float*)d_in[0];
    const float* w1  = (const float*)d_in[1];
    const float* b1  = (const float*)d_in[2];
    const float* w2  = (const float*)d_in[3];
    const float* b2  = (const float*)d_in[4];
    const float* wfc = (const float*)d_in[5];
    const float* bfc = (const float*)d_in[6];
    float* out = (float*)d_out;

    cudaFuncSetAttribute(conv1_kernel, cudaFuncAttributeMaxDynamicSharedMemorySize,
                         C1_TOTAL);
    cudaFuncSetAttribute(conv2_kernel, cudaFuncAttributeMaxDynamicSharedMemorySize,
                         C2_TOTAL);

    prep_w1_kernel<<<3, 1024>>>(w1);
    prep_w2_kernel<<<36, 1024>>>(w2);
    conv1_kernel<<<dim3(196, 32), 256, C1_TOTAL>>>(x, b1);
    conv2_kernel<<<dim3(98, 32), 256, C2_TOTAL>>>(b2);
    fc_partial_kernel<<<dim3(196, 4), 256>>>(wfc);
    fc_reduce_kernel<<<32, 224>>>(bfc, out);
}